// round 2
// baseline (speedup 1.0000x reference)
#include <cuda_runtime.h>
#include <cuda_bf16.h>

// ---------------------------------------------------------------------------
// Problem constants (shapes are fixed by the dataset; sizes re-derived at launch)
// ---------------------------------------------------------------------------
#define NMAX   100000
#define DFEAT  64
#define OUTF   128

// Scratch (no cudaMalloc allowed): ~51 MB of __device__ globals.
__device__ float g_hs[(size_t)NMAX * DFEAT];   // relu(h_src @ W1 + b1)
__device__ float g_vs[(size_t)NMAX * DFEAT];   // scatter-sum accumulator
__device__ float g_ws[NMAX];                   // per-dst sum of edge weights
__device__ float g_sumsq;                      // global sum of squares

// ---------------------------------------------------------------------------
// Kernel 0: zero the accumulators (must happen every launch — graph replays)
// ---------------------------------------------------------------------------
__global__ void zero_kernel(int n_dst) {
    long tid    = (long)blockIdx.x * blockDim.x + threadIdx.x;
    long stride = (long)gridDim.x * blockDim.x;
    long nv4    = ((long)n_dst * DFEAT) >> 2;   // float4 count
    float4* vs4 = reinterpret_cast<float4*>(g_vs);
    float4 z4 = make_float4(0.f, 0.f, 0.f, 0.f);
    for (long i = tid; i < nv4; i += stride) vs4[i] = z4;
    for (long i = tid; i < n_dst; i += stride) g_ws[i] = 0.f;
    if (tid == 0) g_sumsq = 0.f;
}

// ---------------------------------------------------------------------------
// Kernel 1: hs = relu(h_src @ W1 + b1)    [N,64] @ [64,64]
// Tile: 64 rows x 64 cols per block, 256 threads, 4x4 register micro-tile.
// ---------------------------------------------------------------------------
#define XS1 68   // padded stride: conflict-free row-group broadcasts
__global__ void __launch_bounds__(256) gemm1_kernel(
    const float* __restrict__ X, const float* __restrict__ W,
    const float* __restrict__ b, int N)
{
    __shared__ float Ws[64 * 64];
    __shared__ float Xs[64 * XS1];

    int t    = threadIdx.x;
    int row0 = blockIdx.x * 64;

    for (int i = t; i < 64 * 64; i += 256) Ws[i] = W[i];
    for (int i = t; i < 64 * 64; i += 256) {
        int r = i >> 6, c = i & 63;
        int gr = row0 + r;
        Xs[r * XS1 + c] = (gr < N) ? X[(size_t)gr * DFEAT + c] : 0.f;
    }
    __syncthreads();

    int tr = t >> 4;          // 0..15 -> rows tr*4..tr*4+3
    int tc = t & 15;          // 0..15 -> cols tc*4..tc*4+3

    float acc[4][4];
#pragma unroll
    for (int i = 0; i < 4; i++)
#pragma unroll
        for (int j = 0; j < 4; j++) acc[i][j] = 0.f;

#pragma unroll 8
    for (int k = 0; k < 64; k++) {
        float a0 = Xs[(tr * 4 + 0) * XS1 + k];
        float a1 = Xs[(tr * 4 + 1) * XS1 + k];
        float a2 = Xs[(tr * 4 + 2) * XS1 + k];
        float a3 = Xs[(tr * 4 + 3) * XS1 + k];
        float4 bb = *reinterpret_cast<const float4*>(&Ws[k * 64 + tc * 4]);
        acc[0][0] += a0 * bb.x; acc[0][1] += a0 * bb.y; acc[0][2] += a0 * bb.z; acc[0][3] += a0 * bb.w;
        acc[1][0] += a1 * bb.x; acc[1][1] += a1 * bb.y; acc[1][2] += a1 * bb.z; acc[1][3] += a1 * bb.w;
        acc[2][0] += a2 * bb.x; acc[2][1] += a2 * bb.y; acc[2][2] += a2 * bb.z; acc[2][3] += a2 * bb.w;
        acc[3][0] += a3 * bb.x; acc[3][1] += a3 * bb.y; acc[3][2] += a3 * bb.z; acc[3][3] += a3 * bb.w;
    }

    float4 bv = *reinterpret_cast<const float4*>(&b[tc * 4]);
#pragma unroll
    for (int i = 0; i < 4; i++) {
        int gr = row0 + tr * 4 + i;
        if (gr < N) {
            float4 o;
            o.x = fmaxf(acc[i][0] + bv.x, 0.f);
            o.y = fmaxf(acc[i][1] + bv.y, 0.f);
            o.z = fmaxf(acc[i][2] + bv.z, 0.f);
            o.w = fmaxf(acc[i][3] + bv.w, 0.f);
            *reinterpret_cast<float4*>(&g_hs[(size_t)gr * DFEAT + tc * 4]) = o;
        }
    }
}

// ---------------------------------------------------------------------------
// Kernel 2: edge scatter. 2 edges per warp, 16 lanes per edge.
//   sub-lane l (0..15): v4 = hs[src][4l..4l+3] * w
//                       atomicAdd(float4) into vs[dst][4l..4l+3]
//   sub-lane 0:         atomicAdd(ws[dst], w)
// float4 red = 1 RED.E.ADD.F32 x4 -> 4x fewer atomic transactions vs scalar.
// ---------------------------------------------------------------------------
__global__ void __launch_bounds__(256) scatter_kernel(
    const float* __restrict__ ew, const int* __restrict__ src,
    const int* __restrict__ dst, int E)
{
    int warp = (blockIdx.x * blockDim.x + threadIdx.x) >> 5;
    int lane = threadIdx.x & 31;
    int eid  = warp * 2 + (lane >> 4);   // 2 edges per warp
    int sub  = lane & 15;
    if (eid >= E) return;

    int   s = __ldg(&src[eid]);
    int   d = __ldg(&dst[eid]);
    float w = __ldg(&ew[eid]);

    float4 v = *reinterpret_cast<const float4*>(&g_hs[(size_t)s * DFEAT + sub * 4]);
    v.x *= w; v.y *= w; v.z *= w; v.w *= w;
    atomicAdd(reinterpret_cast<float4*>(&g_vs[(size_t)d * DFEAT + sub * 4]), v);
    if (sub == 0) atomicAdd(&g_ws[d], w);
}

// ---------------------------------------------------------------------------
// Kernel 3: new = relu(concat([vs/clip(ws,1), h_dst]) @ W2 + b2)  [N,128]@[128,128]
// Tile: 64 rows x 64 cols (gridDim.y=2 col halves), 256 threads, 4x4 micro-tile.
// Also accumulates the global sum of squares.
// Dynamic smem: Ws 128*64 + Xs 64*132 floats = 66560 B.
// ---------------------------------------------------------------------------
#define XS2 132
#define GEMM2_SMEM ((128 * 64 + 64 * XS2) * (int)sizeof(float))
__global__ void __launch_bounds__(256) gemm2_kernel(
    const float* __restrict__ hdst, const float* __restrict__ W2,
    const float* __restrict__ b2, float* __restrict__ out, int N)
{
    extern __shared__ float sm[];
    float* Ws = sm;                 // [128][64]  column slice
    float* Xs = sm + 128 * 64;      // [64][XS2]

    int t    = threadIdx.x;
    int row0 = blockIdx.x * 64;
    int col0 = blockIdx.y * 64;

    for (int i = t; i < 128 * 64; i += 256) {
        int k = i >> 6, c = i & 63;
        Ws[i] = W2[(size_t)k * OUTF + col0 + c];
    }
    for (int i = t; i < 64 * 128; i += 256) {
        int r = i >> 7, k = i & 127;
        int gr = row0 + r;
        float v = 0.f;
        if (gr < N) {
            if (k < 64) {
                float w = fmaxf(g_ws[gr], 1.0f);
                v = g_vs[(size_t)gr * DFEAT + k] / w;
            } else {
                v = hdst[(size_t)gr * DFEAT + (k - 64)];
            }
        }
        Xs[r * XS2 + k] = v;
    }
    __syncthreads();

    int tr = t >> 4;
    int tc = t & 15;

    float acc[4][4];
#pragma unroll
    for (int i = 0; i < 4; i++)
#pragma unroll
        for (int j = 0; j < 4; j++) acc[i][j] = 0.f;

#pragma unroll 8
    for (int k = 0; k < 128; k++) {
        float a0 = Xs[(tr * 4 + 0) * XS2 + k];
        float a1 = Xs[(tr * 4 + 1) * XS2 + k];
        float a2 = Xs[(tr * 4 + 2) * XS2 + k];
        float a3 = Xs[(tr * 4 + 3) * XS2 + k];
        float4 bb = *reinterpret_cast<const float4*>(&Ws[k * 64 + tc * 4]);
        acc[0][0] += a0 * bb.x; acc[0][1] += a0 * bb.y; acc[0][2] += a0 * bb.z; acc[0][3] += a0 * bb.w;
        acc[1][0] += a1 * bb.x; acc[1][1] += a1 * bb.y; acc[1][2] += a1 * bb.z; acc[1][3] += a1 * bb.w;
        acc[2][0] += a2 * bb.x; acc[2][1] += a2 * bb.y; acc[2][2] += a2 * bb.z; acc[2][3] += a2 * bb.w;
        acc[3][0] += a3 * bb.x; acc[3][1] += a3 * bb.y; acc[3][2] += a3 * bb.z; acc[3][3] += a3 * bb.w;
    }

    float4 bv = *reinterpret_cast<const float4*>(&b2[col0 + tc * 4]);
    float ss = 0.f;
#pragma unroll
    for (int i = 0; i < 4; i++) {
        int gr = row0 + tr * 4 + i;
        if (gr < N) {
            float4 o;
            o.x = fmaxf(acc[i][0] + bv.x, 0.f);
            o.y = fmaxf(acc[i][1] + bv.y, 0.f);
            o.z = fmaxf(acc[i][2] + bv.z, 0.f);
            o.w = fmaxf(acc[i][3] + bv.w, 0.f);
            *reinterpret_cast<float4*>(&out[(size_t)gr * OUTF + col0 + tc * 4]) = o;
            ss += o.x * o.x + o.y * o.y + o.z * o.z + o.w * o.w;
        }
    }

    // Block-reduce ss -> atomicAdd(g_sumsq). Reuse Xs after a sync.
#pragma unroll
    for (int o = 16; o > 0; o >>= 1) ss += __shfl_down_sync(0xffffffffu, ss, o);
    __syncthreads();                       // all compute reads of Xs done
    if ((t & 31) == 0) Xs[t >> 5] = ss;
    __syncthreads();
    if (t == 0) {
        float v = 0.f;
#pragma unroll
        for (int i = 0; i < 8; i++) v += Xs[i];
        atomicAdd(&g_sumsq, v);
    }
}

// ---------------------------------------------------------------------------
// Kernel 4: out *= rsqrt(sumsq)
// ---------------------------------------------------------------------------
__global__ void scale_kernel(float* __restrict__ out, long n4) {
    float inv = rsqrtf(g_sumsq);
    long tid    = (long)blockIdx.x * blockDim.x + threadIdx.x;
    long stride = (long)gridDim.x * blockDim.x;
    float4* o4 = reinterpret_cast<float4*>(out);
    for (long i = tid; i < n4; i += stride) {
        float4 v = o4[i];
        v.x *= inv; v.y *= inv; v.z *= inv; v.w *= inv;
        o4[i] = v;
    }
}

// ---------------------------------------------------------------------------
// Launch
// ---------------------------------------------------------------------------
extern "C" void kernel_launch(void* const* d_in, const int* in_sizes, int n_in,
                              void* d_out, int out_size)
{
    const float* h_src = (const float*)d_in[0];
    const float* h_dst = (const float*)d_in[1];
    const float* ew    = (const float*)d_in[2];
    const float* W1    = (const float*)d_in[3];
    const float* b1    = (const float*)d_in[4];
    const float* W2    = (const float*)d_in[5];
    const float* b2    = (const float*)d_in[6];
    const int*   src   = (const int*)  d_in[7];
    const int*   dst   = (const int*)  d_in[8];
    float*       out   = (float*)d_out;

    int Ns = in_sizes[0] / DFEAT;   // 100000
    int Nd = in_sizes[1] / DFEAT;   // 100000
    int E  = in_sizes[2];           // 1250000

    cudaFuncSetAttribute(gemm2_kernel,
                         cudaFuncAttributeMaxDynamicSharedMemorySize, GEMM2_SMEM);

    zero_kernel<<<2048, 256>>>(Nd);
    gemm1_kernel<<<(Ns + 63) / 64, 256>>>(h_src, W1, b1, Ns);
    // 2 edges per warp, 8 warps per 256-thread block -> 16 edges/block
    scatter_kernel<<<(E + 15) / 16, 256>>>(ew, src, dst, E);
    dim3 g2((Nd + 63) / 64, 2);
    gemm2_kernel<<<g2, 256, GEMM2_SMEM>>>(h_dst, W2, b2, out, Nd);
    long n4 = ((long)Nd * OUTF) >> 2;
    scale_kernel<<<2048, 256>>>(out, n4);
}

// round 5
// speedup vs baseline: 1.4190x; 1.4190x over previous
#include <cuda_runtime.h>
#include <cuda_bf16.h>

#define NMAX   100000
#define DFEAT  64
#define OUTF   128

// Skewed shared layout for X tiles: row r starts at r*68 + (r>>3)*4 floats.
// Rows 8 apart differ by 548 ≡ 4 (mod 32) banks -> conflict-free row-group
// broadcasts in the 8-row micro-tiles.
#define XOFF(r) ((r) * 68 + ((r) >> 3) * 4)
#define XSZ     8768   // > XOFF(127)+68 = 8764

// Scratch (no cudaMalloc allowed).
__device__ float g_hs[(size_t)NMAX * DFEAT];   // relu(h_src @ W1 + b1)
__device__ float g_vs[(size_t)NMAX * DFEAT];   // scatter-sum accumulator
__device__ float g_ws[NMAX];                   // per-dst sum of edge weights
__device__ float g_sumsq;                      // global sum of squares

// ---------------------------------------------------------------------------
// Kernel 0: zero accumulators (graph replays -> every launch)
// ---------------------------------------------------------------------------
__global__ void zero_kernel(int n_dst) {
    long tid    = (long)blockIdx.x * blockDim.x + threadIdx.x;
    long stride = (long)gridDim.x * blockDim.x;
    long nv4    = ((long)n_dst * DFEAT) >> 2;
    float4* vs4 = reinterpret_cast<float4*>(g_vs);
    float4 z4 = make_float4(0.f, 0.f, 0.f, 0.f);
    for (long i = tid; i < nv4; i += stride) vs4[i] = z4;
    for (long i = tid; i < n_dst; i += stride) g_ws[i] = 0.f;
    if (tid == 0) g_sumsq = 0.f;
}

// ---------------------------------------------------------------------------
// Kernel 1: hs = relu(h_src @ W1 + b1)   [N,64] @ [64,64]
// Block tile 128 rows x 64 cols, 256 threads, 8x4 micro-tile, skewed Xs.
// Dynamic smem: (4096 + XSZ) floats = 51456 B (exceeds 48KB static limit).
// ---------------------------------------------------------------------------
#define GEMM1_SMEM ((64 * 64 + XSZ) * (int)sizeof(float))
__global__ void __launch_bounds__(256) gemm1_kernel(
    const float* __restrict__ X, const float* __restrict__ W,
    const float* __restrict__ b, int N)
{
    extern __shared__ float sm1[];
    float* Ws = sm1;            // [64][64], same layout as W1
    float* Xs = sm1 + 64 * 64;  // skewed [128][64]

    int t    = threadIdx.x;
    int row0 = blockIdx.x * 128;

    // Ws: 4096 floats = 1024 float4
    for (int i = t; i < 1024; i += 256)
        reinterpret_cast<float4*>(Ws)[i] = reinterpret_cast<const float4*>(W)[i];
    // Xs: 128 rows x 16 float4
    for (int i = t; i < 2048; i += 256) {
        int r = i >> 4, k4 = i & 15;
        int gr = row0 + r;
        float4 v = make_float4(0.f, 0.f, 0.f, 0.f);
        if (gr < N) v = *reinterpret_cast<const float4*>(&X[(size_t)gr * DFEAT + k4 * 4]);
        *reinterpret_cast<float4*>(&Xs[XOFF(r) + k4 * 4]) = v;
    }
    __syncthreads();

    int tr = t >> 4;   // 0..15 -> rows tr*8..tr*8+7
    int tc = t & 15;   // 0..15 -> cols tc*4..tc*4+3

    int xb[8];
#pragma unroll
    for (int i = 0; i < 8; i++) xb[i] = XOFF(tr * 8 + i);

    float acc[8][4];
#pragma unroll
    for (int i = 0; i < 8; i++)
#pragma unroll
        for (int j = 0; j < 4; j++) acc[i][j] = 0.f;

#pragma unroll 4
    for (int k = 0; k < 64; k++) {
        float4 bb = *reinterpret_cast<const float4*>(&Ws[k * 64 + tc * 4]);
#pragma unroll
        for (int i = 0; i < 8; i++) {
            float a = Xs[xb[i] + k];
            acc[i][0] += a * bb.x; acc[i][1] += a * bb.y;
            acc[i][2] += a * bb.z; acc[i][3] += a * bb.w;
        }
    }

    float4 bv = *reinterpret_cast<const float4*>(&b[tc * 4]);
#pragma unroll
    for (int i = 0; i < 8; i++) {
        int gr = row0 + tr * 8 + i;
        if (gr < N) {
            float4 o;
            o.x = fmaxf(acc[i][0] + bv.x, 0.f);
            o.y = fmaxf(acc[i][1] + bv.y, 0.f);
            o.z = fmaxf(acc[i][2] + bv.z, 0.f);
            o.w = fmaxf(acc[i][3] + bv.w, 0.f);
            *reinterpret_cast<float4*>(&g_hs[(size_t)gr * DFEAT + tc * 4]) = o;
        }
    }
}

// ---------------------------------------------------------------------------
// Kernel 2: edge scatter. 2 edges/warp, 16 lanes/edge, float4 atomics.
// ---------------------------------------------------------------------------
__global__ void __launch_bounds__(256) scatter_kernel(
    const float* __restrict__ ew, const int* __restrict__ src,
    const int* __restrict__ dst, int E)
{
    int warp = (blockIdx.x * blockDim.x + threadIdx.x) >> 5;
    int lane = threadIdx.x & 31;
    int eid  = warp * 2 + (lane >> 4);
    int sub  = lane & 15;
    if (eid >= E) return;

    int   s = __ldg(&src[eid]);
    int   d = __ldg(&dst[eid]);
    float w = __ldg(&ew[eid]);

    float4 v = *reinterpret_cast<const float4*>(&g_hs[(size_t)s * DFEAT + sub * 4]);
    v.x *= w; v.y *= w; v.z *= w; v.w *= w;
    atomicAdd(reinterpret_cast<float4*>(&g_vs[(size_t)d * DFEAT + sub * 4]), v);
    if (sub == 0) atomicAdd(&g_ws[d], w);
}

// ---------------------------------------------------------------------------
// Kernel 3: new = relu(concat([vs/clip(ws,1), h_dst]) @ W2 + b2)  [N,128]@[128,128]
// Block tile 128 rows x 128 cols, 256 threads, 8x8 micro-tile.
// K split into two 64-chunks aligned with the concat: chunk0=nv, chunk1=h_dst.
// Dynamic smem: Ws 64*128 + Xs XSZ floats = 67840 B.
// ---------------------------------------------------------------------------
#define GEMM2_SMEM ((64 * 128 + XSZ) * (int)sizeof(float))
__global__ void __launch_bounds__(256, 2) gemm2_kernel(
    const float* __restrict__ hdst, const float* __restrict__ W2,
    const float* __restrict__ b2, float* __restrict__ out, int N)
{
    extern __shared__ float sm[];
    float* Wsm = sm;            // [64][128] k-chunk of W2
    float* Xs  = sm + 64 * 128; // skewed [128][64]

    int t    = threadIdx.x;
    int row0 = blockIdx.x * 128;

    int tr = t >> 4;   // 0..15 -> rows tr*8..
    int tc = t & 15;   // 0..15 -> cols tc*8..

    int xb[8];
#pragma unroll
    for (int i = 0; i < 8; i++) xb[i] = XOFF(tr * 8 + i);

    float acc[8][8];
#pragma unroll
    for (int i = 0; i < 8; i++)
#pragma unroll
        for (int j = 0; j < 8; j++) acc[i][j] = 0.f;

#pragma unroll
    for (int c = 0; c < 2; c++) {
        // Load W2 chunk: rows c*64..c*64+63, all 128 cols. 2048 float4.
        for (int i = t; i < 2048; i += 256) {
            reinterpret_cast<float4*>(Wsm)[i] =
                *reinterpret_cast<const float4*>(&W2[(size_t)c * 64 * OUTF + i * 4]);
        }
        // Load X chunk: 128 rows x 16 float4
        for (int i = t; i < 2048; i += 256) {
            int r = i >> 4, k4 = i & 15;
            int gr = row0 + r;
            float4 v = make_float4(0.f, 0.f, 0.f, 0.f);
            if (gr < N) {
                if (c == 0) {
                    float inv = 1.0f / fmaxf(g_ws[gr], 1.0f);
                    v = *reinterpret_cast<const float4*>(&g_vs[(size_t)gr * DFEAT + k4 * 4]);
                    v.x *= inv; v.y *= inv; v.z *= inv; v.w *= inv;
                } else {
                    v = *reinterpret_cast<const float4*>(&hdst[(size_t)gr * DFEAT + k4 * 4]);
                }
            }
            *reinterpret_cast<float4*>(&Xs[XOFF(r) + k4 * 4]) = v;
        }
        __syncthreads();

#pragma unroll 4
        for (int k = 0; k < 64; k++) {
            float4 b0 = *reinterpret_cast<const float4*>(&Wsm[k * 128 + tc * 8]);
            float4 b1 = *reinterpret_cast<const float4*>(&Wsm[k * 128 + tc * 8 + 4]);
            float a[8];
#pragma unroll
            for (int i = 0; i < 8; i++) a[i] = Xs[xb[i] + k];
#pragma unroll
            for (int i = 0; i < 8; i++) {
                acc[i][0] += a[i] * b0.x; acc[i][1] += a[i] * b0.y;
                acc[i][2] += a[i] * b0.z; acc[i][3] += a[i] * b0.w;
                acc[i][4] += a[i] * b1.x; acc[i][5] += a[i] * b1.y;
                acc[i][6] += a[i] * b1.z; acc[i][7] += a[i] * b1.w;
            }
        }
        __syncthreads();
    }

    float4 bv0 = *reinterpret_cast<const float4*>(&b2[tc * 8]);
    float4 bv1 = *reinterpret_cast<const float4*>(&b2[tc * 8 + 4]);
    float ss = 0.f;
#pragma unroll
    for (int i = 0; i < 8; i++) {
        int gr = row0 + tr * 8 + i;
        if (gr < N) {
            float4 o0, o1;
            o0.x = fmaxf(acc[i][0] + bv0.x, 0.f);
            o0.y = fmaxf(acc[i][1] + bv0.y, 0.f);
            o0.z = fmaxf(acc[i][2] + bv0.z, 0.f);
            o0.w = fmaxf(acc[i][3] + bv0.w, 0.f);
            o1.x = fmaxf(acc[i][4] + bv1.x, 0.f);
            o1.y = fmaxf(acc[i][5] + bv1.y, 0.f);
            o1.z = fmaxf(acc[i][6] + bv1.z, 0.f);
            o1.w = fmaxf(acc[i][7] + bv1.w, 0.f);
            float* op = &out[(size_t)gr * OUTF + tc * 8];
            *reinterpret_cast<float4*>(op)     = o0;
            *reinterpret_cast<float4*>(op + 4) = o1;
            ss += o0.x * o0.x + o0.y * o0.y + o0.z * o0.z + o0.w * o0.w;
            ss += o1.x * o1.x + o1.y * o1.y + o1.z * o1.z + o1.w * o1.w;
        }
    }

    // Block-reduce ss -> g_sumsq
#pragma unroll
    for (int o = 16; o > 0; o >>= 1) ss += __shfl_down_sync(0xffffffffu, ss, o);
    __syncthreads();
    if ((t & 31) == 0) Wsm[t >> 5] = ss;
    __syncthreads();
    if (t == 0) {
        float v = 0.f;
#pragma unroll
        for (int i = 0; i < 8; i++) v += Wsm[i];
        atomicAdd(&g_sumsq, v);
    }
}

// ---------------------------------------------------------------------------
// Kernel 4: out *= rsqrt(sumsq)
// ---------------------------------------------------------------------------
__global__ void scale_kernel(float* __restrict__ out, long n4) {
    float inv = rsqrtf(g_sumsq);
    long tid    = (long)blockIdx.x * blockDim.x + threadIdx.x;
    long stride = (long)gridDim.x * blockDim.x;
    float4* o4 = reinterpret_cast<float4*>(out);
    for (long i = tid; i < n4; i += stride) {
        float4 v = o4[i];
        v.x *= inv; v.y *= inv; v.z *= inv; v.w *= inv;
        o4[i] = v;
    }
}

// ---------------------------------------------------------------------------
// Launch
// ---------------------------------------------------------------------------
extern "C" void kernel_launch(void* const* d_in, const int* in_sizes, int n_in,
                              void* d_out, int out_size)
{
    const float* h_src = (const float*)d_in[0];
    const float* h_dst = (const float*)d_in[1];
    const float* ew    = (const float*)d_in[2];
    const float* W1    = (const float*)d_in[3];
    const float* b1    = (const float*)d_in[4];
    const float* W2    = (const float*)d_in[5];
    const float* b2    = (const float*)d_in[6];
    const int*   src   = (const int*)  d_in[7];
    const int*   dst   = (const int*)  d_in[8];
    float*       out   = (float*)d_out;

    int Ns = in_sizes[0] / DFEAT;   // 100000
    int Nd = in_sizes[1] / DFEAT;   // 100000
    int E  = in_sizes[2];           // 1250000

    cudaFuncSetAttribute(gemm1_kernel,
                         cudaFuncAttributeMaxDynamicSharedMemorySize, GEMM1_SMEM);
    cudaFuncSetAttribute(gemm2_kernel,
                         cudaFuncAttributeMaxDynamicSharedMemorySize, GEMM2_SMEM);

    zero_kernel<<<2048, 256>>>(Nd);
    gemm1_kernel<<<(Ns + 127) / 128, 256, GEMM1_SMEM>>>(h_src, W1, b1, Ns);
    scatter_kernel<<<(E + 15) / 16, 256>>>(ew, src, dst, E);
    gemm2_kernel<<<(Nd + 127) / 128, 256, GEMM2_SMEM>>>(h_dst, W2, b2, out, Nd);
    long n4 = ((long)Nd * OUTF) >> 2;
    scale_kernel<<<2048, 256>>>(out, n4);
}